// round 16
// baseline (speedup 1.0000x reference)
#include <cuda_runtime.h>
#include <cuda_fp16.h>
#include <math.h>
#include <stdint.h>

// Problem constants
#define T_SEQ   2048
#define B_SZ    2
#define E_DIM   2048
#define H_Q     16
#define H_KV    4
#define D_HEAD  128
#define M_ROWS  4096        // B*T
#define WIN     512

// 1/sqrt(128) * log2(e): folded into Q at pack time; softmax uses exp2
#define QSCALE2 (0.08838834764831845f * 1.4426950408889634f)

// ---------------------------------------------------------------------------
// Scratch (device globals)
// ---------------------------------------------------------------------------
__device__ float g_cos[T_SEQ * 64];
__device__ float g_sin[T_SEQ * 64];

__device__ __half g_x16 [M_ROWS * E_DIM];
__device__ __half g_wq16[(H_Q  * D_HEAD) * E_DIM];
__device__ __half g_wk16[(H_KV * D_HEAD) * E_DIM];
__device__ __half g_wv16[(H_KV * D_HEAD) * E_DIM];
__device__ __half g_wo16[E_DIM * E_DIM];
__device__ __half g_a16 [M_ROWS * E_DIM];

__device__ __half g_q16p[B_SZ * H_Q  * T_SEQ * D_HEAD];  // [b][h][t][d], RoPE'd + pre-scaled
__device__ __half g_k16p[B_SZ * H_KV * T_SEQ * D_HEAD];  // [b][kv][t][d], RoPE'd
__device__ __half g_vt16[B_SZ * H_KV * D_HEAD * T_SEQ];  // [b][kv][d][t]

// ---------------------------------------------------------------------------
// fused fp32 -> fp16 convert for 5 arrays + RoPE table build (one launch)
// ---------------------------------------------------------------------------
#define NX_ELEM (M_ROWS * E_DIM)
#define NQ_ELEM (H_Q * D_HEAD * E_DIM)
#define NK_ELEM (H_KV * D_HEAD * E_DIM)
#define CONV_G0 (NX_ELEM / 4)
#define CONV_G1 (CONV_G0 + NQ_ELEM / 4)
#define CONV_G2 (CONV_G1 + NK_ELEM / 4)
#define CONV_G3 (CONV_G2 + NK_ELEM / 4)
#define CONV_G4 (CONV_G3 + NQ_ELEM / 4)
#define CONV_G5 (CONV_G4 + (T_SEQ * 64) / 4)     // + rope table groups

__global__ void conv_all_kernel(const float* __restrict__ x,
                                const float* __restrict__ wq,
                                const float* __restrict__ wk,
                                const float* __restrict__ wv,
                                const float* __restrict__ wo)
{
    int g = blockIdx.x * 256 + threadIdx.x;
    if (g >= CONV_G5) return;
    if (g >= CONV_G4) {
        // RoPE table: 4 entries per thread
        int base = (g - CONV_G4) * 4;
        #pragma unroll
        for (int j = 0; j < 4; j++) {
            int idx = base + j;
            int i = idx & 63;
            int t = idx >> 6;
            float ex = (float)(2 * i) * (1.0f / 128.0f);
            float invf = (float)(1.0 / pow(10000.0, (double)ex));
            float ang = (float)t * invf;
            double s, c;
            sincos((double)ang, &s, &c);
            g_cos[idx] = (float)c;
            g_sin[idx] = (float)s;
        }
        return;
    }
    const float* s;
    __half* d;
    if (g < CONV_G0)      { s = x;  d = g_x16; }
    else if (g < CONV_G1) { s = wq; d = g_wq16; g -= CONV_G0; }
    else if (g < CONV_G2) { s = wk; d = g_wk16; g -= CONV_G1; }
    else if (g < CONV_G3) { s = wv; d = g_wv16; g -= CONV_G2; }
    else                  { s = wo; d = g_wo16; g -= CONV_G3; }
    int i = g * 4;
    float4 v = *(const float4*)(s + i);
    __half2 lo = __floats2half2_rn(v.x, v.y);
    __half2 hi = __floats2half2_rn(v.z, v.w);
    uint2 pk;
    pk.x = *(uint32_t*)&lo;
    pk.y = *(uint32_t*)&hi;
    *(uint2*)(d + i) = pk;
}

// ---------------------------------------------------------------------------
// fp16 GEMM mainloop (NT), 128x128 tile, 3-stage cp.async, fp32 accumulate
// ---------------------------------------------------------------------------
#define GK_BK        64
#define GK_TILE_B    16384
#define GK_STAGE_B   32768
#define GK_SMEM      (1024 + 3 * GK_STAGE_B)
#define TILE_PITCH   132

#define SWZ128(o) ((o) ^ (((o) >> 3) & 0x70))

static __device__ __forceinline__ uint32_t s2u(const void* p) {
    uint32_t a;
    asm("{ .reg .u64 t; cvta.to.shared.u64 t, %1; cvt.u32.u64 %0, t; }" : "=r"(a) : "l"(p));
    return a;
}

#define LDSM_X4(r, addr)                                                      \
    asm volatile("ldmatrix.sync.aligned.m8n8.x4.shared.b16 {%0,%1,%2,%3}, [%4];" \
        : "=r"((r)[0]), "=r"((r)[1]), "=r"((r)[2]), "=r"((r)[3]) : "r"(addr))

#define MMA16816F(d, a, b0, b1)                                               \
    asm volatile("mma.sync.aligned.m16n8k16.row.col.f32.f16.f16.f32 "         \
        "{%0,%1,%2,%3}, {%4,%5,%6,%7}, {%8,%9}, {%0,%1,%2,%3};"               \
        : "+f"((d)[0]), "+f"((d)[1]), "+f"((d)[2]), "+f"((d)[3])              \
        : "r"((a)[0]), "r"((a)[1]), "r"((a)[2]), "r"((a)[3]),                 \
          "r"(b0), "r"(b1))

static __device__ __forceinline__ void gemm_mainloop(
    const __half* A, const __half* B, int bm, int bn, int K,
    uint32_t stages, float acc[4][4][4])
{
    const int tid  = threadIdx.x;
    const int wid  = tid >> 5;
    const int lane = tid & 31;
    const int NC = K / GK_BK;

    const char* gA = (const char*)(A + (size_t)bm * K);
    const char* gB = (const char*)(B + (size_t)bn * K);

    const int rowK2 = K * 2;
    const int r0    = tid >> 3;
    const int c16   = (tid & 7) * 16;

    auto load_chunk = [&](int c, int st) {
        uint32_t sbs = stages + st * GK_STAGE_B;
        long koff = (long)c * GK_BK * 2;
        #pragma unroll
        for (int r = 0; r < 4; r++) {
            int row = r0 + r * 32;
            uint32_t dst = sbs + SWZ128(row * 128 + c16);
            asm volatile("cp.async.cg.shared.global [%0], [%1], 16;"
                         :: "r"(dst), "l"(gA + (size_t)row * rowK2 + koff + c16) : "memory");
            asm volatile("cp.async.cg.shared.global [%0], [%1], 16;"
                         :: "r"(dst + GK_TILE_B), "l"(gB + (size_t)row * rowK2 + koff + c16) : "memory");
        }
    };

    const int wm = wid >> 2;
    const int wn = wid & 3;

    #pragma unroll
    for (int mt = 0; mt < 4; mt++)
        #pragma unroll
        for (int nt = 0; nt < 4; nt++)
            #pragma unroll
            for (int e = 0; e < 4; e++) acc[mt][nt][e] = 0.0f;

    #pragma unroll
    for (int p = 0; p < 2; p++) {
        load_chunk(p, p);
        asm volatile("cp.async.commit_group;" ::: "memory");
    }

    const int a_row  = wm * 64 + (lane & 15);
    const int a_byte = (lane >> 4) * 16;
    const int b_row  = wn * 32 + (lane & 7) + ((lane >> 4) << 3);
    const int b_byte = ((lane >> 3) & 1) << 4;

    for (int c = 0; c < NC; c++) {
        asm volatile("cp.async.wait_group 1;" ::: "memory");
        __syncthreads();

        if (c + 2 < NC) {
            load_chunk(c + 2, (c + 2) % 3);
        }
        asm volatile("cp.async.commit_group;" ::: "memory");

        uint32_t tA = stages + (c % 3) * GK_STAGE_B;
        uint32_t tB = tA + GK_TILE_B;

        #pragma unroll
        for (int ks = 0; ks < 4; ks++) {
            const int kb = ks * 32;
            uint32_t a_f[4][4], b_f[2][4];
            #pragma unroll
            for (int mt = 0; mt < 4; mt++) {
                uint32_t off = SWZ128((a_row + mt * 16) * 128 + kb + a_byte);
                LDSM_X4(a_f[mt], tA + off);
            }
            #pragma unroll
            for (int g = 0; g < 2; g++) {
                uint32_t off = SWZ128((b_row + g * 16) * 128 + kb + b_byte);
                LDSM_X4(b_f[g], tB + off);
            }
            #pragma unroll
            for (int mt = 0; mt < 4; mt++) {
                #pragma unroll
                for (int nt = 0; nt < 4; nt++) {
                    const int g = nt >> 1;
                    const int o = (nt & 1) * 2;
                    MMA16816F(acc[mt][nt], a_f[mt], b_f[g][o], b_f[g][o + 1]);
                }
            }
        }
    }
    __syncthreads();
}

static __device__ __forceinline__ void acc_to_tile(
    float* tile, const float acc[4][4][4], int wid, int lane)
{
    const int wm = wid >> 2;
    const int wn = wid & 3;
    #pragma unroll
    for (int mt = 0; mt < 4; mt++) {
        #pragma unroll
        for (int nt = 0; nt < 4; nt++) {
            int rr = wm * 64 + mt * 16 + (lane >> 2);
            int cc = wn * 32 + nt * 8 + (lane & 3) * 2;
            tile[rr * TILE_PITCH + cc]           = acc[mt][nt][0];
            tile[rr * TILE_PITCH + cc + 1]       = acc[mt][nt][1];
            tile[(rr + 8) * TILE_PITCH + cc]     = acc[mt][nt][2];
            tile[(rr + 8) * TILE_PITCH + cc + 1] = acc[mt][nt][3];
        }
    }
}

// ---------------------------------------------------------------------------
// fused QKV projection + RoPE + fp16 pack (Q pre-scaled by QSCALE2).
// ---------------------------------------------------------------------------
__global__ void __launch_bounds__(256, 2)
qkv_gemm(const __half* __restrict__ X,
         const __half* __restrict__ Wq, const __half* __restrict__ Wk,
         const __half* __restrict__ Wv,
         __half* __restrict__ q16p, __half* __restrict__ k16p,
         __half* __restrict__ vt16)
{
    extern __shared__ char smem_raw[];
    uint32_t stages = (s2u(smem_raw) + 1023) & ~1023u;
    float* tile = (float*)(smem_raw + (stages - s2u(smem_raw)));

    const int tid  = threadIdx.x;
    const int wid  = tid >> 5;
    const int lane = tid & 31;
    const int bx = blockIdx.x;
    const int bm = blockIdx.y * 128;

    const __half* B;
    int bn;
    if (bx < 16)      { B = Wq; bn = bx * 128; }
    else if (bx < 20) { B = Wk; bn = (bx - 16) * 128; }
    else              { B = Wv; bn = (bx - 20) * 128; }

    float acc[4][4][4];
    gemm_mainloop(X, B, bm, bn, E_DIM, stages, acc);

    acc_to_tile(tile, acc, wid, lane);
    __syncthreads();

    const int bb = bm >> 11;
    const int tb = bm & 2047;

    if (bx < 20) {
        const bool isq = (bx < 16);
        const float postmul = isq ? QSCALE2 : 1.0f;
        __half* dstbase;
        if (isq) dstbase = q16p + ((size_t)(bb * H_Q + bx) * T_SEQ) * D_HEAD;
        else     dstbase = k16p + ((size_t)(bb * H_KV + (bx - 16)) * T_SEQ) * D_HEAD;
        int r  = tid >> 1;
        int d0 = (tid & 1) * 32;
        int t  = tb + r;
        __half* dst = dstbase + (size_t)t * D_HEAD;
        __half lo[32], hi[32];
        #pragma unroll
        for (int j = 0; j < 32; j++) {
            int d = d0 + j;
            float x1 = tile[r * TILE_PITCH + d];
            float x2 = tile[r * TILE_PITCH + d + 64];
            float c = g_cos[t * 64 + d];
            float s = g_sin[t * 64 + d];
            lo[j] = __float2half((x1 * c - x2 * s) * postmul);
            hi[j] = __float2half((x2 * c + x1 * s) * postmul);
        }
        #pragma unroll
        for (int q8 = 0; q8 < 4; q8++) {
            *(uint4*)(dst + d0 + q8 * 8)      = *(uint4*)(lo + q8 * 8);
            *(uint4*)(dst + d0 + 64 + q8 * 8) = *(uint4*)(hi + q8 * 8);
        }
    } else {
        int kv = bx - 20;
        int d  = tid >> 1;
        int th = (tid & 1) * 64;
        __half* dst = vt16 + ((size_t)((bb * H_KV + kv) * D_HEAD + d)) * T_SEQ + tb + th;
        __half hv[64];
        #pragma unroll
        for (int j = 0; j < 64; j++)
            hv[j] = __float2half(tile[(th + j) * TILE_PITCH + d]);
        #pragma unroll
        for (int q8 = 0; q8 < 8; q8++)
            *(uint4*)(dst + q8 * 8) = *(uint4*)(hv + q8 * 8);
    }
}

// plain GEMM (output projection, fp32 out)
__global__ void __launch_bounds__(256, 2)
h_gemm(const __half* __restrict__ A, const __half* __restrict__ B,
       float* __restrict__ C, int M, int N, int K)
{
    extern __shared__ char smem_raw[];
    uint32_t stages = (s2u(smem_raw) + 1023) & ~1023u;
    const int wid  = threadIdx.x >> 5;
    const int lane = threadIdx.x & 31;
    const int bm = blockIdx.y * 128;
    const int bn = blockIdx.x * 128;

    float acc[4][4][4];
    gemm_mainloop(A, B, bm, bn, K, stages, acc);

    const int wm = wid >> 2;
    const int wn = wid & 3;
    #pragma unroll
    for (int mt = 0; mt < 4; mt++) {
        #pragma unroll
        for (int nt = 0; nt < 4; nt++) {
            int rr = bm + wm * 64 + mt * 16 + (lane >> 2);
            int cc = bn + wn * 32 + nt * 8 + (lane & 3) * 2;
            *(float2*)(C + (size_t)rr * N + cc) =
                make_float2(acc[mt][nt][0], acc[mt][nt][1]);
            *(float2*)(C + (size_t)(rr + 8) * N + cc) =
                make_float2(acc[mt][nt][2], acc[mt][nt][3]);
        }
    }
}

// ---------------------------------------------------------------------------
// fp16 flash attention (R15 pipeline): K 3-stage + V 2-stage rings, one
// barrier/iter, prefetch-before-compute. Softmax via ex2.approx.f16x2:
// fp32 score pair -> half2 -> one f16x2 MUFU -> result IS the PV fragment;
// row-sum taken from the fp16 p values (upconverted).
// smem: Q 32K + K 3x16K + V 2x16K = 112K -> 2 CTAs/SM.
// ---------------------------------------------------------------------------
#define AT_Q_B     32768
#define AT_KSTG_B  16384
#define AT_VSTG_B  16384
#define AT_KOFF    AT_Q_B
#define AT_VOFF    (AT_Q_B + 3 * AT_KSTG_B)
#define AT_SMEM    (AT_VOFF + 2 * AT_VSTG_B)

__global__ void __launch_bounds__(256, 2) attn_mma_kernel(
    const __half* __restrict__ q16, const __half* __restrict__ k16,
    const __half* __restrict__ vt16, __half* __restrict__ o)
{
    extern __shared__ char smem_raw[];
    const uint32_t sb   = s2u(smem_raw);
    const int tid  = threadIdx.x;
    const int w    = tid >> 5;
    const int lane = tid & 31;
    const int qs   = ((int)gridDim.x - 1 - (int)blockIdx.x) * 128;  // heavy first
    const int h    = blockIdx.y;
    const int b    = blockIdx.z;
    const int kvh  = h >> 2;

    const char* qb  = (const char*)(q16 + ((size_t)(b * H_Q + h) * T_SEQ + qs) * D_HEAD);
    const char* kb_ = (const char*)(k16 + (size_t)(b * H_KV + kvh) * T_SEQ * D_HEAD);
    const char* vb_ = (const char*)(vt16 + (size_t)(b * H_KV + kvh) * D_HEAD * T_SEQ);

    const int kb0 = (qs >= WIN) ? qs - WIN : 0;
    const int NB  = ((qs + 64 - kb0) >> 6) + 1;

    auto load_k = [&](int kb, int st) {
        uint32_t base = sb + AT_KOFF + st * AT_KSTG_B;
        const char* ks = kb_ + (size_t)kb * 256;
        #pragma unroll
        for (int j = 0; j < 4; j++) {
            uint32_t off = (uint32_t)tid * 64 + j * 16;
            asm volatile("cp.async.cg.shared.global [%0], [%1], 16;"
                         :: "r"(base + SWZ128(off)), "l"(ks + off) : "memory");
        }
    };

    auto load_v = [&](int kb, int st) {
        uint32_t base = sb + AT_VOFF + st * AT_VSTG_B;
        #pragma unroll
        for (int j = 0; j < 4; j++) {
            uint32_t off = (uint32_t)tid * 64 + j * 16;
            uint32_t row = off >> 7;
            uint32_t col = off & 127;
            const char* src = vb_ + ((size_t)row * T_SEQ + kb) * 2 + col;
            asm volatile("cp.async.cg.shared.global [%0], [%1], 16;"
                         :: "r"(base + SWZ128(off)), "l"(src) : "memory");
        }
    };

    // prologue: Q + K0 + V0 -> group 0; K1 -> group 1
    #pragma unroll
    for (int j = 0; j < 8; j++) {
        asm volatile("cp.async.cg.shared.global [%0], [%1], 16;"
                     :: "r"(sb + SWZ128(tid * 128 + j * 16)),
                        "l"(qb + tid * 128 + j * 16) : "memory");
    }
    load_k(kb0, 0);
    load_v(kb0, 0);
    asm volatile("cp.async.commit_group;" ::: "memory");
    load_k(kb0 + 64, 1);
    asm volatile("cp.async.commit_group;" ::: "memory");

    float O[16][4];
    #pragma unroll
    for (int nt = 0; nt < 16; nt++)
        #pragma unroll
        for (int e = 0; e < 4; e++) O[nt][e] = 0.0f;
    float l0 = 0.0f, l1 = 0.0f;

    const int r0g = qs + w * 16 + (lane >> 2);
    const int r1g = r0g + 8;
    const int wrmin = qs + w * 16;
    const int wrmax = wrmin + 15;

    for (int i = 0; i < NB; i++) {
        const int kb = kb0 + i * 64;

        asm volatile("cp.async.wait_group 1;" ::: "memory");
        __syncthreads();

        if (i + 1 < NB) load_v(kb0 + (i + 1) * 64, (i + 1) & 1);
        asm volatile("cp.async.commit_group;" ::: "memory");
        if (i + 2 < NB) load_k(kb0 + (i + 2) * 64, (i + 2) % 3);
        asm volatile("cp.async.commit_group;" ::: "memory");

        const bool active = (kb + 63 >= wrmin - (WIN - 1)) && (kb <= wrmax);
        if (active) {
            const uint32_t kbase = sb + AT_KOFF + (i % 3) * AT_KSTG_B;
            const uint32_t vbase = sb + AT_VOFF + (i & 1) * AT_VSTG_B;

            float sreg[8][4];
            #pragma unroll
            for (int t = 0; t < 8; t++)
                #pragma unroll
                for (int e = 0; e < 4; e++) sreg[t][e] = 0.0f;

            #pragma unroll
            for (int ks = 0; ks < 8; ks++) {
                const int khalf = ks >> 2;
                const int kb32  = (ks & 3) * 32;
                uint32_t a[4];
                {
                    uint32_t vrow = (uint32_t)(w * 16 + (lane & 15)) * 2 + khalf;
                    LDSM_X4(a, sb + SWZ128(vrow * 128 + kb32 + (lane >> 4) * 16));
                }
                #pragma unroll
                for (int g = 0; g < 4; g++) {
                    uint32_t bf[4];
                    uint32_t vrow = (uint32_t)(g * 16 + (lane & 7) + ((lane >> 4) << 3)) * 2 + khalf;
                    LDSM_X4(bf, kbase + SWZ128(vrow * 128 + kb32 + (((lane >> 3) & 1) << 4)));
                    MMA16816F(sreg[g * 2],     a, bf[0], bf[1]);
                    MMA16816F(sreg[g * 2 + 1], a, bf[2], bf[3]);
                }
            }

            const bool full = (kb + 63 <= wrmin) && (kb >= wrmax - (WIN - 1));
            if (!full) {
                #pragma unroll
                for (int t = 0; t < 8; t++) {
                    int c0 = kb + t * 8 + (lane & 3) * 2;
                    int c1 = c0 + 1;
                    sreg[t][0] = (c0 <= r0g && r0g - c0 < WIN) ? sreg[t][0] : -1e30f;
                    sreg[t][1] = (c1 <= r0g && r0g - c1 < WIN) ? sreg[t][1] : -1e30f;
                    sreg[t][2] = (c0 <= r1g && r1g - c0 < WIN) ? sreg[t][2] : -1e30f;
                    sreg[t][3] = (c1 <= r1g && r1g - c1 < WIN) ? sreg[t][3] : -1e30f;
                }
            }

            // f16x2 softmax: cvt pair -> ex2.approx.f16x2 -> p fragment + sum
            uint32_t ph[4][4];
            float sum0 = 0.0f, sum1 = 0.0f;
            #pragma unroll
            for (int t = 0; t < 8; t++) {
                __half2 sa = __floats2half2_rn(sreg[t][0], sreg[t][1]);
                __half2 sbb = __floats2half2_rn(sreg[t][2], sreg[t][3]);
                uint32_t ea, eb;
                asm("ex2.approx.f16x2 %0, %1;" : "=r"(ea) : "r"(*(uint32_t*)&sa));
                asm("ex2.approx.f16x2 %0, %1;" : "=r"(eb) : "r"(*(uint32_t*)&sbb));
                float2 fa = __half22float2(*(__half2*)&ea);
                float2 fb = __half22float2(*(__half2*)&eb);
                sum0 += fa.x + fa.y;
                sum1 += fb.x + fb.y;
                const int f = t >> 1;
                if ((t & 1) == 0) { ph[f][0] = ea; ph[f][1] = eb; }
                else              { ph[f][2] = ea; ph[f][3] = eb; }
            }
            l0 += sum0;
            l1 += sum1;

            #pragma unroll
            for (int f = 0; f < 4; f++) {
                #pragma unroll
                for (int g = 0; g < 8; g++) {
                    uint32_t bf[4];
                    uint32_t vrow = (uint32_t)(g * 16 + (lane & 7) + ((lane >> 4) << 3));
                    uint32_t off = SWZ128(vrow * 128 + f * 32 + (((lane >> 3) & 1) << 4));
                    LDSM_X4(bf, vbase + off);
                    MMA16816F(O[2 * g],     ph[f], bf[0], bf[1]);
                    MMA16816F(O[2 * g + 1], ph[f], bf[2], bf[3]);
                }
            }
        }
    }

    l0 += __shfl_xor_sync(0xffffffffu, l0, 1);
    l0 += __shfl_xor_sync(0xffffffffu, l0, 2);
    l1 += __shfl_xor_sync(0xffffffffu, l1, 1);
    l1 += __shfl_xor_sync(0xffffffffu, l1, 2);

    float invl0 = 1.0f / l0;
    float invl1 = 1.0f / l1;
    #pragma unroll
    for (int nt = 0; nt < 16; nt++) {
        int col = nt * 8 + (lane & 3) * 2;
        __half* d0 = o + ((size_t)(b * T_SEQ + r0g)) * E_DIM + h * D_HEAD + col;
        __half* d1 = o + ((size_t)(b * T_SEQ + r1g)) * E_DIM + h * D_HEAD + col;
        __half2 h0 = __floats2half2_rn(O[nt][0] * invl0, O[nt][1] * invl0);
        __half2 h1 = __floats2half2_rn(O[nt][2] * invl1, O[nt][3] * invl1);
        *(__half2*)d0 = h0;
        *(__half2*)d1 = h1;
    }
}

// ---------------------------------------------------------------------------
// launch
// ---------------------------------------------------------------------------
extern "C" void kernel_launch(void* const* d_in, const int* in_sizes, int n_in,
                              void* d_out, int out_size)
{
    const float* x  = (const float*)d_in[0];
    const float* Wq = (const float*)d_in[1];
    const float* Wk = (const float*)d_in[2];
    const float* Wv = (const float*)d_in[3];
    const float* Wo = (const float*)d_in[4];
    float* out = (float*)d_out;

    __half *x16, *wq16, *wk16, *wv16, *wo16, *a16, *q16p, *k16p, *vt16;
    cudaGetSymbolAddress((void**)&x16,  g_x16);
    cudaGetSymbolAddress((void**)&wq16, g_wq16);
    cudaGetSymbolAddress((void**)&wk16, g_wk16);
    cudaGetSymbolAddress((void**)&wv16, g_wv16);
    cudaGetSymbolAddress((void**)&wo16, g_wo16);
    cudaGetSymbolAddress((void**)&a16,  g_a16);
    cudaGetSymbolAddress((void**)&q16p, g_q16p);
    cudaGetSymbolAddress((void**)&k16p, g_k16p);
    cudaGetSymbolAddress((void**)&vt16, g_vt16);

    cudaFuncSetAttribute(qkv_gemm, cudaFuncAttributeMaxDynamicSharedMemorySize, GK_SMEM);
    cudaFuncSetAttribute(h_gemm, cudaFuncAttributeMaxDynamicSharedMemorySize, GK_SMEM);
    cudaFuncSetAttribute(attn_mma_kernel, cudaFuncAttributeMaxDynamicSharedMemorySize, AT_SMEM);

    // fused: fp16 conversions + RoPE table (one launch)
    conv_all_kernel<<<(CONV_G5 + 255) / 256, 256>>>(x, Wq, Wk, Wv, Wo);

    qkv_gemm<<<dim3(24, 32), 256, GK_SMEM>>>(x16, wq16, wk16, wv16, q16p, k16p, vt16);

    attn_mma_kernel<<<dim3(T_SEQ / 128, H_Q, B_SZ), 256, AT_SMEM>>>(q16p, k16p, vt16, a16);

    h_gemm<<<dim3(E_DIM / 128, M_ROWS / 128), 256, GK_SMEM>>>(
        a16, wo16, out, M_ROWS, E_DIM, E_DIM);
}

// round 17
// speedup vs baseline: 1.1366x; 1.1366x over previous
#include <cuda_runtime.h>
#include <cuda_fp16.h>
#include <math.h>
#include <stdint.h>

// Problem constants
#define T_SEQ   2048
#define B_SZ    2
#define E_DIM   2048
#define H_Q     16
#define H_KV    4
#define D_HEAD  128
#define M_ROWS  4096        // B*T
#define WIN     512

// 1/sqrt(128) * log2(e): folded into Q at pack time; softmax uses exp2
#define QSCALE2 (0.08838834764831845f * 1.4426950408889634f)

// ---------------------------------------------------------------------------
// Scratch (device globals)
// ---------------------------------------------------------------------------
__device__ float g_cos[T_SEQ * 64];
__device__ float g_sin[T_SEQ * 64];

__device__ __half g_x16 [M_ROWS * E_DIM];
__device__ __half g_wq16[(H_Q  * D_HEAD) * E_DIM];
__device__ __half g_wk16[(H_KV * D_HEAD) * E_DIM];
__device__ __half g_wv16[(H_KV * D_HEAD) * E_DIM];
__device__ __half g_wo16[E_DIM * E_DIM];
__device__ __half g_a16 [M_ROWS * E_DIM];

__device__ __half g_q16p[B_SZ * H_Q  * T_SEQ * D_HEAD];  // [b][h][t][d], RoPE'd + pre-scaled
__device__ __half g_k16p[B_SZ * H_KV * T_SEQ * D_HEAD];  // [b][kv][t][d], RoPE'd
__device__ __half g_vt16[B_SZ * H_KV * D_HEAD * T_SEQ];  // [b][kv][d][t]

// ---------------------------------------------------------------------------
// RoPE tables (standalone, 512 blocks: fp64 sincos well spread across SMs)
// ---------------------------------------------------------------------------
__global__ void rope_table_kernel() {
    int idx = blockIdx.x * 256 + threadIdx.x;
    if (idx >= T_SEQ * 64) return;
    int i = idx & 63;
    int t = idx >> 6;
    float ex = (float)(2 * i) * (1.0f / 128.0f);
    float invf = (float)(1.0 / pow(10000.0, (double)ex));
    float ang = (float)t * invf;
    double s, c;
    sincos((double)ang, &s, &c);
    g_cos[idx] = (float)c;
    g_sin[idx] = (float)s;
}

// ---------------------------------------------------------------------------
// fused fp32 -> fp16 convert for 5 arrays (one launch)
// ---------------------------------------------------------------------------
#define NX_ELEM (M_ROWS * E_DIM)
#define NQ_ELEM (H_Q * D_HEAD * E_DIM)
#define NK_ELEM (H_KV * D_HEAD * E_DIM)
#define CONV_G0 (NX_ELEM / 4)
#define CONV_G1 (CONV_G0 + NQ_ELEM / 4)
#define CONV_G2 (CONV_G1 + NK_ELEM / 4)
#define CONV_G3 (CONV_G2 + NK_ELEM / 4)
#define CONV_G4 (CONV_G3 + NQ_ELEM / 4)

__global__ void conv_all_kernel(const float* __restrict__ x,
                                const float* __restrict__ wq,
                                const float* __restrict__ wk,
                                const float* __restrict__ wv,
                                const float* __restrict__ wo)
{
    int g = blockIdx.x * 256 + threadIdx.x;
    if (g >= CONV_G4) return;
    const float* s;
    __half* d;
    if (g < CONV_G0)      { s = x;  d = g_x16; }
    else if (g < CONV_G1) { s = wq; d = g_wq16; g -= CONV_G0; }
    else if (g < CONV_G2) { s = wk; d = g_wk16; g -= CONV_G1; }
    else if (g < CONV_G3) { s = wv; d = g_wv16; g -= CONV_G2; }
    else                  { s = wo; d = g_wo16; g -= CONV_G3; }
    int i = g * 4;
    float4 v = *(const float4*)(s + i);
    __half2 lo = __floats2half2_rn(v.x, v.y);
    __half2 hi = __floats2half2_rn(v.z, v.w);
    uint2 pk;
    pk.x = *(uint32_t*)&lo;
    pk.y = *(uint32_t*)&hi;
    *(uint2*)(d + i) = pk;
}

// ---------------------------------------------------------------------------
// fp16 GEMM mainloop (NT), 128x128 tile, 3-stage cp.async, fp32 accumulate
// ---------------------------------------------------------------------------
#define GK_BK        64
#define GK_TILE_B    16384
#define GK_STAGE_B   32768
#define GK_SMEM      (1024 + 3 * GK_STAGE_B)
#define TILE_PITCH   132

#define SWZ128(o) ((o) ^ (((o) >> 3) & 0x70))

static __device__ __forceinline__ uint32_t s2u(const void* p) {
    uint32_t a;
    asm("{ .reg .u64 t; cvta.to.shared.u64 t, %1; cvt.u32.u64 %0, t; }" : "=r"(a) : "l"(p));
    return a;
}

#define LDSM_X4(r, addr)                                                      \
    asm volatile("ldmatrix.sync.aligned.m8n8.x4.shared.b16 {%0,%1,%2,%3}, [%4];" \
        : "=r"((r)[0]), "=r"((r)[1]), "=r"((r)[2]), "=r"((r)[3]) : "r"(addr))

#define MMA16816F(d, a, b0, b1)                                               \
    asm volatile("mma.sync.aligned.m16n8k16.row.col.f32.f16.f16.f32 "         \
        "{%0,%1,%2,%3}, {%4,%5,%6,%7}, {%8,%9}, {%0,%1,%2,%3};"               \
        : "+f"((d)[0]), "+f"((d)[1]), "+f"((d)[2]), "+f"((d)[3])              \
        : "r"((a)[0]), "r"((a)[1]), "r"((a)[2]), "r"((a)[3]),                 \
          "r"(b0), "r"(b1))

static __device__ __forceinline__ void gemm_mainloop(
    const __half* A, const __half* B, int bm, int bn, int K,
    uint32_t stages, float acc[4][4][4])
{
    const int tid  = threadIdx.x;
    const int wid  = tid >> 5;
    const int lane = tid & 31;
    const int NC = K / GK_BK;

    const char* gA = (const char*)(A + (size_t)bm * K);
    const char* gB = (const char*)(B + (size_t)bn * K);

    const int rowK2 = K * 2;
    const int r0    = tid >> 3;
    const int c16   = (tid & 7) * 16;

    auto load_chunk = [&](int c, int st) {
        uint32_t sbs = stages + st * GK_STAGE_B;
        long koff = (long)c * GK_BK * 2;
        #pragma unroll
        for (int r = 0; r < 4; r++) {
            int row = r0 + r * 32;
            uint32_t dst = sbs + SWZ128(row * 128 + c16);
            asm volatile("cp.async.cg.shared.global [%0], [%1], 16;"
                         :: "r"(dst), "l"(gA + (size_t)row * rowK2 + koff + c16) : "memory");
            asm volatile("cp.async.cg.shared.global [%0], [%1], 16;"
                         :: "r"(dst + GK_TILE_B), "l"(gB + (size_t)row * rowK2 + koff + c16) : "memory");
        }
    };

    const int wm = wid >> 2;
    const int wn = wid & 3;

    #pragma unroll
    for (int mt = 0; mt < 4; mt++)
        #pragma unroll
        for (int nt = 0; nt < 4; nt++)
            #pragma unroll
            for (int e = 0; e < 4; e++) acc[mt][nt][e] = 0.0f;

    #pragma unroll
    for (int p = 0; p < 2; p++) {
        load_chunk(p, p);
        asm volatile("cp.async.commit_group;" ::: "memory");
    }

    const int a_row  = wm * 64 + (lane & 15);
    const int a_byte = (lane >> 4) * 16;
    const int b_row  = wn * 32 + (lane & 7) + ((lane >> 4) << 3);
    const int b_byte = ((lane >> 3) & 1) << 4;

    for (int c = 0; c < NC; c++) {
        asm volatile("cp.async.wait_group 1;" ::: "memory");
        __syncthreads();

        if (c + 2 < NC) {
            load_chunk(c + 2, (c + 2) % 3);
        }
        asm volatile("cp.async.commit_group;" ::: "memory");

        uint32_t tA = stages + (c % 3) * GK_STAGE_B;
        uint32_t tB = tA + GK_TILE_B;

        #pragma unroll
        for (int ks = 0; ks < 4; ks++) {
            const int kb = ks * 32;
            uint32_t a_f[4][4], b_f[2][4];
            #pragma unroll
            for (int mt = 0; mt < 4; mt++) {
                uint32_t off = SWZ128((a_row + mt * 16) * 128 + kb + a_byte);
                LDSM_X4(a_f[mt], tA + off);
            }
            #pragma unroll
            for (int g = 0; g < 2; g++) {
                uint32_t off = SWZ128((b_row + g * 16) * 128 + kb + b_byte);
                LDSM_X4(b_f[g], tB + off);
            }
            #pragma unroll
            for (int mt = 0; mt < 4; mt++) {
                #pragma unroll
                for (int nt = 0; nt < 4; nt++) {
                    const int g = nt >> 1;
                    const int o = (nt & 1) * 2;
                    MMA16816F(acc[mt][nt], a_f[mt], b_f[g][o], b_f[g][o + 1]);
                }
            }
        }
    }
    __syncthreads();
}

static __device__ __forceinline__ void acc_to_tile(
    float* tile, const float acc[4][4][4], int wid, int lane)
{
    const int wm = wid >> 2;
    const int wn = wid & 3;
    #pragma unroll
    for (int mt = 0; mt < 4; mt++) {
        #pragma unroll
        for (int nt = 0; nt < 4; nt++) {
            int rr = wm * 64 + mt * 16 + (lane >> 2);
            int cc = wn * 32 + nt * 8 + (lane & 3) * 2;
            tile[rr * TILE_PITCH + cc]           = acc[mt][nt][0];
            tile[rr * TILE_PITCH + cc + 1]       = acc[mt][nt][1];
            tile[(rr + 8) * TILE_PITCH + cc]     = acc[mt][nt][2];
            tile[(rr + 8) * TILE_PITCH + cc + 1] = acc[mt][nt][3];
        }
    }
}

// ---------------------------------------------------------------------------
// fused QKV projection + RoPE + fp16 pack (Q pre-scaled by QSCALE2).
// ---------------------------------------------------------------------------
__global__ void __launch_bounds__(256, 2)
qkv_gemm(const __half* __restrict__ X,
         const __half* __restrict__ Wq, const __half* __restrict__ Wk,
         const __half* __restrict__ Wv,
         __half* __restrict__ q16p, __half* __restrict__ k16p,
         __half* __restrict__ vt16)
{
    extern __shared__ char smem_raw[];
    uint32_t stages = (s2u(smem_raw) + 1023) & ~1023u;
    float* tile = (float*)(smem_raw + (stages - s2u(smem_raw)));

    const int tid  = threadIdx.x;
    const int wid  = tid >> 5;
    const int lane = tid & 31;
    const int bx = blockIdx.x;
    const int bm = blockIdx.y * 128;

    const __half* B;
    int bn;
    if (bx < 16)      { B = Wq; bn = bx * 128; }
    else if (bx < 20) { B = Wk; bn = (bx - 16) * 128; }
    else              { B = Wv; bn = (bx - 20) * 128; }

    float acc[4][4][4];
    gemm_mainloop(X, B, bm, bn, E_DIM, stages, acc);

    acc_to_tile(tile, acc, wid, lane);
    __syncthreads();

    const int bb = bm >> 11;
    const int tb = bm & 2047;

    if (bx < 20) {
        const bool isq = (bx < 16);
        const float postmul = isq ? QSCALE2 : 1.0f;
        __half* dstbase;
        if (isq) dstbase = q16p + ((size_t)(bb * H_Q + bx) * T_SEQ) * D_HEAD;
        else     dstbase = k16p + ((size_t)(bb * H_KV + (bx - 16)) * T_SEQ) * D_HEAD;
        int r  = tid >> 1;
        int d0 = (tid & 1) * 32;
        int t  = tb + r;
        __half* dst = dstbase + (size_t)t * D_HEAD;
        __half lo[32], hi[32];
        #pragma unroll
        for (int j = 0; j < 32; j++) {
            int d = d0 + j;
            float x1 = tile[r * TILE_PITCH + d];
            float x2 = tile[r * TILE_PITCH + d + 64];
            float c = g_cos[t * 64 + d];
            float s = g_sin[t * 64 + d];
            lo[j] = __float2half((x1 * c - x2 * s) * postmul);
            hi[j] = __float2half((x2 * c + x1 * s) * postmul);
        }
        #pragma unroll
        for (int q8 = 0; q8 < 4; q8++) {
            *(uint4*)(dst + d0 + q8 * 8)      = *(uint4*)(lo + q8 * 8);
            *(uint4*)(dst + d0 + 64 + q8 * 8) = *(uint4*)(hi + q8 * 8);
        }
    } else {
        int kv = bx - 20;
        int d  = tid >> 1;
        int th = (tid & 1) * 64;
        __half* dst = vt16 + ((size_t)((bb * H_KV + kv) * D_HEAD + d)) * T_SEQ + tb + th;
        __half hv[64];
        #pragma unroll
        for (int j = 0; j < 64; j++)
            hv[j] = __float2half(tile[(th + j) * TILE_PITCH + d]);
        #pragma unroll
        for (int q8 = 0; q8 < 8; q8++)
            *(uint4*)(dst + q8 * 8) = *(uint4*)(hv + q8 * 8);
    }
}

// plain GEMM (output projection, fp32 out)
__global__ void __launch_bounds__(256, 2)
h_gemm(const __half* __restrict__ A, const __half* __restrict__ B,
       float* __restrict__ C, int M, int N, int K)
{
    extern __shared__ char smem_raw[];
    uint32_t stages = (s2u(smem_raw) + 1023) & ~1023u;
    const int wid  = threadIdx.x >> 5;
    const int lane = threadIdx.x & 31;
    const int bm = blockIdx.y * 128;
    const int bn = blockIdx.x * 128;

    float acc[4][4][4];
    gemm_mainloop(A, B, bm, bn, K, stages, acc);

    const int wm = wid >> 2;
    const int wn = wid & 3;
    #pragma unroll
    for (int mt = 0; mt < 4; mt++) {
        #pragma unroll
        for (int nt = 0; nt < 4; nt++) {
            int rr = bm + wm * 64 + mt * 16 + (lane >> 2);
            int cc = bn + wn * 32 + nt * 8 + (lane & 3) * 2;
            *(float2*)(C + (size_t)rr * N + cc) =
                make_float2(acc[mt][nt][0], acc[mt][nt][1]);
            *(float2*)(C + (size_t)(rr + 8) * N + cc) =
                make_float2(acc[mt][nt][2], acc[mt][nt][3]);
        }
    }
}

// ---------------------------------------------------------------------------
// fp16 flash attention (R15 pipeline + R16 f16x2 softmax):
// K 3-stage + V 2-stage rings, one barrier/iter, prefetch-before-compute.
// Softmax via ex2.approx.f16x2: fp32 score pair -> half2 -> one f16x2 MUFU
// -> result IS the PV fragment; row-sum from the fp16 p values.
// smem: Q 32K + K 3x16K + V 2x16K = 112K -> 2 CTAs/SM.
// ---------------------------------------------------------------------------
#define AT_Q_B     32768
#define AT_KSTG_B  16384
#define AT_VSTG_B  16384
#define AT_KOFF    AT_Q_B
#define AT_VOFF    (AT_Q_B + 3 * AT_KSTG_B)
#define AT_SMEM    (AT_VOFF + 2 * AT_VSTG_B)

__global__ void __launch_bounds__(256, 2) attn_mma_kernel(
    const __half* __restrict__ q16, const __half* __restrict__ k16,
    const __half* __restrict__ vt16, __half* __restrict__ o)
{
    extern __shared__ char smem_raw[];
    const uint32_t sb   = s2u(smem_raw);
    const int tid  = threadIdx.x;
    const int w    = tid >> 5;
    const int lane = tid & 31;
    const int qs   = ((int)gridDim.x - 1 - (int)blockIdx.x) * 128;  // heavy first
    const int h    = blockIdx.y;
    const int b    = blockIdx.z;
    const int kvh  = h >> 2;

    const char* qb  = (const char*)(q16 + ((size_t)(b * H_Q + h) * T_SEQ + qs) * D_HEAD);
    const char* kb_ = (const char*)(k16 + (size_t)(b * H_KV + kvh) * T_SEQ * D_HEAD);
    const char* vb_ = (const char*)(vt16 + (size_t)(b * H_KV + kvh) * D_HEAD * T_SEQ);

    const int kb0 = (qs >= WIN) ? qs - WIN : 0;
    const int NB  = ((qs + 64 - kb0) >> 6) + 1;

    auto load_k = [&](int kb, int st) {
        uint32_t base = sb + AT_KOFF + st * AT_KSTG_B;
        const char* ks = kb_ + (size_t)kb * 256;
        #pragma unroll
        for (int j = 0; j < 4; j++) {
            uint32_t off = (uint32_t)tid * 64 + j * 16;
            asm volatile("cp.async.cg.shared.global [%0], [%1], 16;"
                         :: "r"(base + SWZ128(off)), "l"(ks + off) : "memory");
        }
    };

    auto load_v = [&](int kb, int st) {
        uint32_t base = sb + AT_VOFF + st * AT_VSTG_B;
        #pragma unroll
        for (int j = 0; j < 4; j++) {
            uint32_t off = (uint32_t)tid * 64 + j * 16;
            uint32_t row = off >> 7;
            uint32_t col = off & 127;
            const char* src = vb_ + ((size_t)row * T_SEQ + kb) * 2 + col;
            asm volatile("cp.async.cg.shared.global [%0], [%1], 16;"
                         :: "r"(base + SWZ128(off)), "l"(src) : "memory");
        }
    };

    // prologue: Q + K0 + V0 -> group 0; K1 -> group 1
    #pragma unroll
    for (int j = 0; j < 8; j++) {
        asm volatile("cp.async.cg.shared.global [%0], [%1], 16;"
                     :: "r"(sb + SWZ128(tid * 128 + j * 16)),
                        "l"(qb + tid * 128 + j * 16) : "memory");
    }
    load_k(kb0, 0);
    load_v(kb0, 0);
    asm volatile("cp.async.commit_group;" ::: "memory");
    load_k(kb0 + 64, 1);
    asm volatile("cp.async.commit_group;" ::: "memory");

    float O[16][4];
    #pragma unroll
    for (int nt = 0; nt < 16; nt++)
        #pragma unroll
        for (int e = 0; e < 4; e++) O[nt][e] = 0.0f;
    float l0 = 0.0f, l1 = 0.0f;

    const int r0g = qs + w * 16 + (lane >> 2);
    const int r1g = r0g + 8;
    const int wrmin = qs + w * 16;
    const int wrmax = wrmin + 15;

    for (int i = 0; i < NB; i++) {
        const int kb = kb0 + i * 64;

        asm volatile("cp.async.wait_group 1;" ::: "memory");
        __syncthreads();

        if (i + 1 < NB) load_v(kb0 + (i + 1) * 64, (i + 1) & 1);
        asm volatile("cp.async.commit_group;" ::: "memory");
        if (i + 2 < NB) load_k(kb0 + (i + 2) * 64, (i + 2) % 3);
        asm volatile("cp.async.commit_group;" ::: "memory");

        const bool active = (kb + 63 >= wrmin - (WIN - 1)) && (kb <= wrmax);
        if (active) {
            const uint32_t kbase = sb + AT_KOFF + (i % 3) * AT_KSTG_B;
            const uint32_t vbase = sb + AT_VOFF + (i & 1) * AT_VSTG_B;

            float sreg[8][4];
            #pragma unroll
            for (int t = 0; t < 8; t++)
                #pragma unroll
                for (int e = 0; e < 4; e++) sreg[t][e] = 0.0f;

            #pragma unroll
            for (int ks = 0; ks < 8; ks++) {
                const int khalf = ks >> 2;
                const int kb32  = (ks & 3) * 32;
                uint32_t a[4];
                {
                    uint32_t vrow = (uint32_t)(w * 16 + (lane & 15)) * 2 + khalf;
                    LDSM_X4(a, sb + SWZ128(vrow * 128 + kb32 + (lane >> 4) * 16));
                }
                #pragma unroll
                for (int g = 0; g < 4; g++) {
                    uint32_t bf[4];
                    uint32_t vrow = (uint32_t)(g * 16 + (lane & 7) + ((lane >> 4) << 3)) * 2 + khalf;
                    LDSM_X4(bf, kbase + SWZ128(vrow * 128 + kb32 + (((lane >> 3) & 1) << 4)));
                    MMA16816F(sreg[g * 2],     a, bf[0], bf[1]);
                    MMA16816F(sreg[g * 2 + 1], a, bf[2], bf[3]);
                }
            }

            const bool full = (kb + 63 <= wrmin) && (kb >= wrmax - (WIN - 1));
            if (!full) {
                #pragma unroll
                for (int t = 0; t < 8; t++) {
                    int c0 = kb + t * 8 + (lane & 3) * 2;
                    int c1 = c0 + 1;
                    sreg[t][0] = (c0 <= r0g && r0g - c0 < WIN) ? sreg[t][0] : -1e30f;
                    sreg[t][1] = (c1 <= r0g && r0g - c1 < WIN) ? sreg[t][1] : -1e30f;
                    sreg[t][2] = (c0 <= r1g && r1g - c0 < WIN) ? sreg[t][2] : -1e30f;
                    sreg[t][3] = (c1 <= r1g && r1g - c1 < WIN) ? sreg[t][3] : -1e30f;
                }
            }

            // f16x2 softmax: cvt pair -> ex2.approx.f16x2 -> p fragment + sum
            uint32_t ph[4][4];
            float sum0 = 0.0f, sum1 = 0.0f;
            #pragma unroll
            for (int t = 0; t < 8; t++) {
                __half2 sa = __floats2half2_rn(sreg[t][0], sreg[t][1]);
                __half2 sbb = __floats2half2_rn(sreg[t][2], sreg[t][3]);
                uint32_t ea, eb;
                asm("ex2.approx.f16x2 %0, %1;" : "=r"(ea) : "r"(*(uint32_t*)&sa));
                asm("ex2.approx.f16x2 %0, %1;" : "=r"(eb) : "r"(*(uint32_t*)&sbb));
                float2 fa = __half22float2(*(__half2*)&ea);
                float2 fb = __half22float2(*(__half2*)&eb);
                sum0 += fa.x + fa.y;
                sum1 += fb.x + fb.y;
                const int f = t >> 1;
                if ((t & 1) == 0) { ph[f][0] = ea; ph[f][1] = eb; }
                else              { ph[f][2] = ea; ph[f][3] = eb; }
            }
            l0 += sum0;
            l1 += sum1;

            #pragma unroll
            for (int f = 0; f < 4; f++) {
                #pragma unroll
                for (int g = 0; g < 8; g++) {
                    uint32_t bf[4];
                    uint32_t vrow = (uint32_t)(g * 16 + (lane & 7) + ((lane >> 4) << 3));
                    uint32_t off = SWZ128(vrow * 128 + f * 32 + (((lane >> 3) & 1) << 4));
                    LDSM_X4(bf, vbase + off);
                    MMA16816F(O[2 * g],     ph[f], bf[0], bf[1]);
                    MMA16816F(O[2 * g + 1], ph[f], bf[2], bf[3]);
                }
            }
        }
    }

    l0 += __shfl_xor_sync(0xffffffffu, l0, 1);
    l0 += __shfl_xor_sync(0xffffffffu, l0, 2);
    l1 += __shfl_xor_sync(0xffffffffu, l1, 1);
    l1 += __shfl_xor_sync(0xffffffffu, l1, 2);

    float invl0 = 1.0f / l0;
    float invl1 = 1.0f / l1;
    #pragma unroll
    for (int nt = 0; nt < 16; nt++) {
        int col = nt * 8 + (lane & 3) * 2;
        __half* d0 = o + ((size_t)(b * T_SEQ + r0g)) * E_DIM + h * D_HEAD + col;
        __half* d1 = o + ((size_t)(b * T_SEQ + r1g)) * E_DIM + h * D_HEAD + col;
        __half2 h0 = __floats2half2_rn(O[nt][0] * invl0, O[nt][1] * invl0);
        __half2 h1 = __floats2half2_rn(O[nt][2] * invl1, O[nt][3] * invl1);
        *(__half2*)d0 = h0;
        *(__half2*)d1 = h1;
    }
}

// ---------------------------------------------------------------------------
// launch
// ---------------------------------------------------------------------------
extern "C" void kernel_launch(void* const* d_in, const int* in_sizes, int n_in,
                              void* d_out, int out_size)
{
    const float* x  = (const float*)d_in[0];
    const float* Wq = (const float*)d_in[1];
    const float* Wk = (const float*)d_in[2];
    const float* Wv = (const float*)d_in[3];
    const float* Wo = (const float*)d_in[4];
    float* out = (float*)d_out;

    __half *x16, *wq16, *wk16, *wv16, *wo16, *a16, *q16p, *k16p, *vt16;
    cudaGetSymbolAddress((void**)&x16,  g_x16);
    cudaGetSymbolAddress((void**)&wq16, g_wq16);
    cudaGetSymbolAddress((void**)&wk16, g_wk16);
    cudaGetSymbolAddress((void**)&wv16, g_wv16);
    cudaGetSymbolAddress((void**)&wo16, g_wo16);
    cudaGetSymbolAddress((void**)&a16,  g_a16);
    cudaGetSymbolAddress((void**)&q16p, g_q16p);
    cudaGetSymbolAddress((void**)&k16p, g_k16p);
    cudaGetSymbolAddress((void**)&vt16, g_vt16);

    cudaFuncSetAttribute(qkv_gemm, cudaFuncAttributeMaxDynamicSharedMemorySize, GK_SMEM);
    cudaFuncSetAttribute(h_gemm, cudaFuncAttributeMaxDynamicSharedMemorySize, GK_SMEM);
    cudaFuncSetAttribute(attn_mma_kernel, cudaFuncAttributeMaxDynamicSharedMemorySize, AT_SMEM);

    rope_table_kernel<<<(T_SEQ * 64 + 255) / 256, 256>>>();

    conv_all_kernel<<<(CONV_G4 + 255) / 256, 256>>>(x, Wq, Wk, Wv, Wo);

    qkv_gemm<<<dim3(24, 32), 256, GK_SMEM>>>(x16, wq16, wk16, wv16, q16p, k16p, vt16);

    attn_mma_kernel<<<dim3(T_SEQ / 128, H_Q, B_SZ), 256, AT_SMEM>>>(q16p, k16p, vt16, a16);

    h_gemm<<<dim3(E_DIM / 128, M_ROWS / 128), 256, GK_SMEM>>>(
        a16, wo16, out, M_ROWS, E_DIM, E_DIM);
}